// round 1
// baseline (speedup 1.0000x reference)
#include <cuda_runtime.h>
#include <math.h>

#define NB 128
#define NP 8732
#define NM 16
#define NC 21

// ---------------- scratch (static device globals; no allocation) ----------------
__device__ float g_overlap[NB * NP];
__device__ int   g_object[NB * NP];
__device__ float g_confneg[NB * NP];
__device__ unsigned long long g_packed[NB * NM];
__device__ int    g_npos[NB];
__device__ int    g_npos_total;
__device__ double g_loc_sum;
__device__ double g_pos_sum;
__device__ double g_hard_sum;

// ---------------- init ----------------
__global__ void init_kernel() {
    int t = blockIdx.x * blockDim.x + threadIdx.x;
    if (t < NB * NM) g_packed[t] = 0ull;
    if (t < NB) g_npos[t] = 0;
    if (t == 0) {
        g_npos_total = 0;
        g_loc_sum = 0.0;
        g_pos_sum = 0.0;
        g_hard_sum = 0.0;
    }
}

// ---------------- matching: per-prior best object + per-object best prior ----------------
// grid: (ceil(NP/256), NB), block 256
__global__ void match_kernel(const float4* __restrict__ boxes,
                             const float4* __restrict__ priors) {
    int b = blockIdx.y;
    int p = blockIdx.x * blockDim.x + threadIdx.x;

    __shared__ float4 sbox[NM];
    __shared__ float  sarea[NM];
    __shared__ unsigned long long swarp[NM][8];

    if (threadIdx.x < NM) {
        float4 bx = boxes[b * NM + threadIdx.x];
        sbox[threadIdx.x] = bx;
        sarea[threadIdx.x] = (bx.z - bx.x) * (bx.w - bx.y);
    }
    __syncthreads();

    bool valid = (p < NP);
    float px1 = 0.f, py1 = 0.f, px2 = 0.f, py2 = 0.f, pa = 1.f;
    if (valid) {
        float4 pr = priors[p];
        px1 = pr.x - 0.5f * pr.z;
        py1 = pr.y - 0.5f * pr.w;
        px2 = pr.x + 0.5f * pr.z;
        py2 = pr.y + 0.5f * pr.w;
        pa = pr.z * pr.w;
    }

    float bestv = -1.0f;
    int   bestm = 0;
    int lane = threadIdx.x & 31;
    int warp = threadIdx.x >> 5;

    #pragma unroll
    for (int m = 0; m < NM; m++) {
        float iou = 0.0f;
        if (valid) {
            float4 bx = sbox[m];
            float lx = fmaxf(bx.x, px1), ly = fmaxf(bx.y, py1);
            float rx = fminf(bx.z, px2), ry = fminf(bx.w, py2);
            float w = fmaxf(rx - lx, 0.0f), h = fmaxf(ry - ly, 0.0f);
            float inter = w * h;
            iou = inter / (sarea[m] + pa - inter);
        }
        // first-max (lowest m) semantics: strict >
        if (iou > bestv) { bestv = iou; bestm = m; }

        // per-object argmax over p: pack (iou_bits, ~p) so ties pick lowest p.
        // iou >= 0 so float bits are monotone as uint.
        unsigned long long key = valid
            ? ((((unsigned long long)__float_as_uint(iou)) << 32)
               | (unsigned long long)(0xFFFFFFFFu - (unsigned)p))
            : 0ull;
        #pragma unroll
        for (int o = 16; o; o >>= 1) {
            unsigned long long other = __shfl_down_sync(0xFFFFFFFFu, key, o);
            if (other > key) key = other;
        }
        if (lane == 0) swarp[m][warp] = key;
    }

    if (valid) {
        g_overlap[b * NP + p] = bestv;
        g_object [b * NP + p] = bestm;
    }
    __syncthreads();
    if (threadIdx.x < NM) {
        unsigned long long key = swarp[threadIdx.x][0];
        #pragma unroll
        for (int w = 1; w < 8; w++)
            if (swarp[threadIdx.x][w] > key) key = swarp[threadIdx.x][w];
        atomicMax(&g_packed[b * NM + threadIdx.x], key);
    }
}

// ---------------- force-assign each object to its best prior (sequential in m: last wins) ----------------
__global__ void force_kernel() {
    int b = blockIdx.x * blockDim.x + threadIdx.x;
    if (b >= NB) return;
    for (int m = 0; m < NM; m++) {
        unsigned long long k = g_packed[b * NM + m];
        int p = (int)(0xFFFFFFFFu - (unsigned)(k & 0xFFFFFFFFull));
        g_object [b * NP + p] = m;
        g_overlap[b * NP + p] = 1.0f;
    }
}

// ---------------- main loss pass: CE per prior, loc L1 for positives, conf_neg ----------------
// grid: (ceil(NP/256), NB), block 256
__global__ void loss_kernel(const float4* __restrict__ plocs,
                            const float*  __restrict__ scores,
                            const float4* __restrict__ boxes,
                            const int*    __restrict__ labels,
                            const float4* __restrict__ priors) {
    int b = blockIdx.y;
    int p = blockIdx.x * blockDim.x + threadIdx.x;
    bool valid = (p < NP);

    double locsum = 0.0, possum = 0.0;
    int cnt = 0;

    if (valid) {
        int idx = b * NP + p;
        float ov = g_overlap[idx];
        int obj  = g_object[idx];
        int label = (ov < 0.5f) ? 0 : labels[b * NM + obj];
        bool pos = (label != 0);

        // cross entropy over NC=21 classes
        float sv[NC];
        const float* s = scores + (size_t)idx * NC;
        #pragma unroll
        for (int c = 0; c < NC; c++) sv[c] = s[c];
        float mx = sv[0];
        #pragma unroll
        for (int c = 1; c < NC; c++) mx = fmaxf(mx, sv[c]);
        float se = 0.0f;
        #pragma unroll
        for (int c = 0; c < NC; c++) se += __expf(sv[c] - mx);
        float conf = __logf(se) + mx - sv[label];

        if (pos) {
            cnt = 1;
            possum = (double)conf;
            float4 bx = boxes[b * NM + obj];
            float cx = 0.5f * (bx.x + bx.z);
            float cy = 0.5f * (bx.y + bx.w);
            float cw = bx.z - bx.x;
            float ch = bx.w - bx.y;
            float4 pr = priors[p];
            float g0 = (cx - pr.x) * 10.0f / pr.z;
            float g1 = (cy - pr.y) * 10.0f / pr.w;
            float g2 = __logf(cw / pr.z) * 5.0f;
            float g3 = __logf(ch / pr.w) * 5.0f;
            float4 pl = plocs[idx];
            locsum = (double)(fabsf(pl.x - g0) + fabsf(pl.y - g1) +
                              fabsf(pl.z - g2) + fabsf(pl.w - g3));
            g_confneg[idx] = 0.0f;
        } else {
            g_confneg[idx] = conf;
        }
    }

    // block reduction
    int lane = threadIdx.x & 31;
    int warp = threadIdx.x >> 5;
    #pragma unroll
    for (int o = 16; o; o >>= 1) {
        locsum += __shfl_down_sync(0xFFFFFFFFu, locsum, o);
        possum += __shfl_down_sync(0xFFFFFFFFu, possum, o);
        cnt    += __shfl_down_sync(0xFFFFFFFFu, cnt, o);
    }
    __shared__ double sl[8], sp[8];
    __shared__ int sc[8];
    if (lane == 0) { sl[warp] = locsum; sp[warp] = possum; sc[warp] = cnt; }
    __syncthreads();
    if (threadIdx.x == 0) {
        double L = 0.0, Q = 0.0;
        int cc = 0;
        #pragma unroll
        for (int w = 0; w < 8; w++) { L += sl[w]; Q += sp[w]; cc += sc[w]; }
        if (L != 0.0) atomicAdd(&g_loc_sum, L);
        if (Q != 0.0) atomicAdd(&g_pos_sum, Q);
        if (cc) {
            atomicAdd(&g_npos[b], cc);
            atomicAdd(&g_npos_total, cc);
        }
    }
}

// ---------------- hard negative mining: exact top-k sum per batch row ----------------
// one block per batch row; exact kth-largest via binary search on float bit patterns
__global__ void hardneg_kernel() {
    int b = blockIdx.x;
    __shared__ float v[NP];
    __shared__ int red[9];
    __shared__ double sred[8];
    int tid = threadIdx.x;
    int lane = tid & 31, warp = tid >> 5;

    for (int i = tid; i < NP; i += blockDim.x) v[i] = g_confneg[b * NP + i];
    __syncthreads();

    int k = 3 * g_npos[b];
    if (k > NP) k = NP;

    // find smallest bit pattern u with count(v > val(u)) < k  =>  val(u) == kth largest
    unsigned lo = 0u, hi = 0x7F800000u;
    while (lo < hi) {
        unsigned mid = (lo + hi) >> 1;
        float t = __uint_as_float(mid);
        int c = 0;
        for (int i = tid; i < NP; i += blockDim.x) c += (v[i] > t);
        #pragma unroll
        for (int o = 16; o; o >>= 1) c += __shfl_down_sync(0xFFFFFFFFu, c, o);
        if (lane == 0) red[warp] = c;
        __syncthreads();
        if (tid == 0) {
            int tot = 0;
            #pragma unroll
            for (int w = 0; w < 8; w++) tot += red[w];
            red[8] = tot;
        }
        __syncthreads();
        int tot = red[8];
        if (tot < k) hi = mid; else lo = mid + 1;
        __syncthreads();
    }
    float t = __uint_as_float(lo);

    double s = 0.0;
    int c = 0;
    for (int i = tid; i < NP; i += blockDim.x) {
        float x = v[i];
        if (x > t) { s += (double)x; c++; }
    }
    #pragma unroll
    for (int o = 16; o; o >>= 1) {
        s += __shfl_down_sync(0xFFFFFFFFu, s, o);
        c += __shfl_down_sync(0xFFFFFFFFu, c, o);
    }
    if (lane == 0) { sred[warp] = s; red[warp] = c; }
    __syncthreads();
    if (tid == 0) {
        double S = 0.0;
        int cc = 0;
        #pragma unroll
        for (int w = 0; w < 8; w++) { S += sred[w]; cc += red[w]; }
        // exact: sum of strictly-greater values + (k - cnt) copies of the kth value
        atomicAdd(&g_hard_sum, S + (double)(k - cc) * (double)t);
    }
}

// ---------------- final combine ----------------
__global__ void final_kernel(float* out) {
    double npos = (double)g_npos_total;
    double conf_loss = (g_hard_sum + g_pos_sum) / npos;
    long long d = 4LL * (long long)g_npos_total;
    if (d < 1) d = 1;
    double loc_loss = g_loc_sum / (double)d;
    out[0] = (float)(conf_loss + loc_loss);
}

// ---------------- launch ----------------
extern "C" void kernel_launch(void* const* d_in, const int* in_sizes, int n_in,
                              void* d_out, int out_size) {
    const float* plocs  = (const float*)d_in[0];  // [B,P,4]
    const float* scores = (const float*)d_in[1];  // [B,P,C]
    const float* boxes  = (const float*)d_in[2];  // [B,M,4]
    const int*   labels = (const int*)d_in[3];    // [B,M]
    const float* priors = (const float*)d_in[4];  // [P,4]

    init_kernel<<<(NB * NM + 255) / 256, 256>>>();

    dim3 gA((NP + 255) / 256, NB);
    match_kernel<<<gA, 256>>>((const float4*)boxes, (const float4*)priors);
    force_kernel<<<1, NB>>>();
    loss_kernel<<<gA, 256>>>((const float4*)plocs, scores,
                             (const float4*)boxes, labels,
                             (const float4*)priors);
    hardneg_kernel<<<NB, 256>>>();
    final_kernel<<<1, 1>>>((float*)d_out);
}

// round 2
// speedup vs baseline: 1.7183x; 1.7183x over previous
#include <cuda_runtime.h>
#include <math.h>

#define NB 128
#define NP 8732
#define NM 16
#define NC 21
#define LBLK 128          // loss block size
#define NLB ((NP + LBLK - 1) / LBLK)   // 69

// ---------------- scratch (static device globals; no allocation) ----------------
__device__ unsigned g_pack[NB * NP];      // (iou bits & ~0xF) | object
__device__ float    g_confneg[NB * NP];
__device__ unsigned long long g_best[NB * NM];
__device__ int    g_npos[NB];
__device__ int    g_npos_total;
__device__ double g_loc_sum;
__device__ double g_pos_sum;
__device__ double g_hard_sum;

// ---------------- init (must run every replay; globals persist) ----------------
__global__ void init_kernel() {
    int t = blockIdx.x * blockDim.x + threadIdx.x;
    if (t < NB * NM) g_best[t] = 0ull;
    if (t < NB) g_npos[t] = 0;
    if (t == 0) {
        g_npos_total = 0;
        g_loc_sum = 0.0;
        g_pos_sum = 0.0;
        g_hard_sum = 0.0;
    }
}

// ---------------- matching ----------------
// grid (ceil(NP/256)=35, NB), block 256.
// Per-prior best object -> g_pack. Per-object best prior via smem transpose
// (16 KB of iou bits) + per-warp reduction (2 objects per warp) -> atomicMax.
__global__ void match_kernel(const float4* __restrict__ boxes,
                             const float4* __restrict__ priors) {
    __shared__ float4 sbox[NM];
    __shared__ float  sarea[NM];
    __shared__ unsigned skey[NM][256];

    int b = blockIdx.y;
    int tid = threadIdx.x;
    int p = blockIdx.x * 256 + tid;

    if (tid < NM) {
        float4 bx = __ldg(&boxes[b * NM + tid]);
        sbox[tid] = bx;
        sarea[tid] = (bx.z - bx.x) * (bx.w - bx.y);
    }
    __syncthreads();

    bool valid = (p < NP);
    float px1 = 0.f, py1 = 0.f, px2 = 0.f, py2 = 0.f, pa = 0.f;
    if (valid) {
        float4 pr = __ldg(&priors[p]);
        px1 = pr.x - 0.5f * pr.z;
        py1 = pr.y - 0.5f * pr.w;
        px2 = pr.x + 0.5f * pr.z;
        py2 = pr.y + 0.5f * pr.w;
        pa = pr.z * pr.w;
    }

    float bestv = -1.0f;
    int   bestm = 0;
    #pragma unroll
    for (int m = 0; m < NM; m++) {
        float iou = 0.0f;
        if (valid) {
            float4 bx = sbox[m];
            float lx = fmaxf(bx.x, px1), ly = fmaxf(bx.y, py1);
            float rx = fminf(bx.z, px2), ry = fminf(bx.w, py2);
            float w = fmaxf(rx - lx, 0.0f), h = fmaxf(ry - ly, 0.0f);
            float inter = w * h;
            iou = __fdividef(inter, sarea[m] + pa - inter);
        }
        skey[m][tid] = __float_as_uint(iou);
        if (iou > bestv) { bestv = iou; bestm = m; }  // strict >: first-max (lowest m)
    }
    if (valid)
        g_pack[b * NP + p] = (__float_as_uint(bestv) & 0xFFFFFFF0u) | (unsigned)bestm;
    __syncthreads();

    int warp = tid >> 5, lane = tid & 31;
    #pragma unroll
    for (int mm = 0; mm < 2; mm++) {
        int m = warp * 2 + mm;
        unsigned long long best = 0ull;
        #pragma unroll
        for (int i = 0; i < 8; i++) {
            int idx = lane + i * 32;
            int pp = blockIdx.x * 256 + idx;
            if (pp < NP) {
                unsigned bits = skey[m][idx];
                // ties pick lowest p (matches jnp.argmax axis=1)
                unsigned long long key = (((unsigned long long)bits) << 32)
                                       | (unsigned long long)(0xFFFFFFFFu - (unsigned)pp);
                if (key > best) best = key;
            }
        }
        #pragma unroll
        for (int o = 16; o; o >>= 1) {
            unsigned long long other = __shfl_down_sync(0xFFFFFFFFu, best, o);
            if (other > best) best = other;
        }
        if (lane == 0) atomicMax(&g_best[b * NM + m], best);
    }
}

// ---------------- force-assign each object to its best prior (m ascending: last wins) ----------------
__global__ void force_kernel() {
    int b = blockIdx.x * blockDim.x + threadIdx.x;
    if (b >= NB) return;
    for (int m = 0; m < NM; m++) {
        unsigned long long k = g_best[b * NM + m];
        int p = (int)(0xFFFFFFFFu - (unsigned)(k & 0xFFFFFFFFull));
        g_pack[b * NP + p] = 0x3F800000u | (unsigned)m;   // ov = 1.0
    }
}

// ---------------- main loss pass: staged score loads, CE, loc L1, conf_neg ----------------
// grid (69, NB), block 128. Scores staged via coalesced float4 -> smem.
__global__ void loss_kernel(const float4* __restrict__ plocs,
                            const float*  __restrict__ scores,
                            const float4* __restrict__ boxes,
                            const int*    __restrict__ labels,
                            const float4* __restrict__ priors) {
    __shared__ float ssc[LBLK * NC];          // 10752 B
    __shared__ float sl[4], sp[4];
    __shared__ int   sc[4];

    int b = blockIdx.y;
    int base = blockIdx.x * LBLK;
    int tid = threadIdx.x;
    int nval = NP - base; if (nval > LBLK) nval = LBLK;

    // stage scores: (b*NP+base)*21 floats, 16B-aligned (NP%4==0, base%4==0), nval*21 % 4 == 0
    const float4* src = (const float4*)(scores + ((size_t)b * NP + base) * NC);
    int nvec = (nval * NC) >> 2;
    for (int i = tid; i < nvec; i += LBLK)
        ((float4*)ssc)[i] = __ldg(&src[i]);
    __syncthreads();

    float locsum = 0.0f, possum = 0.0f;
    int cnt = 0;

    if (tid < nval) {
        int p = base + tid;
        int idx = b * NP + p;
        unsigned pk = g_pack[idx];
        float ov = __uint_as_float(pk & 0xFFFFFFF0u);
        int obj = (int)(pk & 0xFu);
        int label = (ov < 0.5f) ? 0 : labels[b * NM + obj];

        const float* sv = ssc + tid * NC;   // stride 21 words: conflict-free
        float mx = sv[0];
        #pragma unroll
        for (int c = 1; c < NC; c++) mx = fmaxf(mx, sv[c]);
        float se = 0.0f;
        #pragma unroll
        for (int c = 0; c < NC; c++) se += __expf(sv[c] - mx);
        float conf = __logf(se) + mx - sv[label];

        if (label != 0) {
            cnt = 1;
            possum = conf;
            float4 bx = __ldg(&boxes[b * NM + obj]);
            float cx = 0.5f * (bx.x + bx.z);
            float cy = 0.5f * (bx.y + bx.w);
            float cw = bx.z - bx.x;
            float ch = bx.w - bx.y;
            float4 pr = __ldg(&priors[p]);
            float g0 = (cx - pr.x) * 10.0f / pr.z;
            float g1 = (cy - pr.y) * 10.0f / pr.w;
            float g2 = __logf(cw / pr.z) * 5.0f;
            float g3 = __logf(ch / pr.w) * 5.0f;
            float4 pl = __ldg(&plocs[idx]);
            locsum = fabsf(pl.x - g0) + fabsf(pl.y - g1) +
                     fabsf(pl.z - g2) + fabsf(pl.w - g3);
            g_confneg[idx] = 0.0f;
        } else {
            g_confneg[idx] = conf;
        }
    }

    int lane = tid & 31, warp = tid >> 5;
    #pragma unroll
    for (int o = 16; o; o >>= 1) {
        locsum += __shfl_down_sync(0xFFFFFFFFu, locsum, o);
        possum += __shfl_down_sync(0xFFFFFFFFu, possum, o);
        cnt    += __shfl_down_sync(0xFFFFFFFFu, cnt, o);
    }
    if (lane == 0) { sl[warp] = locsum; sp[warp] = possum; sc[warp] = cnt; }
    __syncthreads();
    if (tid == 0) {
        float L = sl[0] + sl[1] + sl[2] + sl[3];
        float Q = sp[0] + sp[1] + sp[2] + sp[3];
        int cc = sc[0] + sc[1] + sc[2] + sc[3];
        if (L != 0.0f) atomicAdd(&g_loc_sum, (double)L);
        if (Q != 0.0f) atomicAdd(&g_pos_sum, (double)Q);
        if (cc) {
            atomicAdd(&g_npos[b], cc);
            atomicAdd(&g_npos_total, cc);
        }
    }
}

// ---------------- hard-negative mining: exact top-k sum, early-exit bit search ----------------
// one block of 1024 threads per batch row
__global__ void __launch_bounds__(1024, 1) hardneg_kernel() {
    int b = blockIdx.x;
    __shared__ unsigned v[NP];       // float bit patterns (values >= 0 -> monotone)
    __shared__ int red[33];
    __shared__ double sred[32];
    int tid = threadIdx.x;
    int lane = tid & 31, warp = tid >> 5;

    for (int i = tid; i < NP; i += 1024)
        v[i] = __float_as_uint(g_confneg[b * NP + i]);
    __syncthreads();

    int k = 3 * g_npos[b];
    if (k > NP) k = NP;

    // find t with count(v > t) == k (early exit), else kth-largest bit pattern
    unsigned lo = 0u, hi = 0x7F800000u;
    while (lo < hi) {
        unsigned mid = (lo + hi) >> 1;
        int c = 0;
        #pragma unroll
        for (int j = 0; j < 9; j++) {
            int i = tid + j * 1024;
            if (i < NP) c += (v[i] > mid);
        }
        #pragma unroll
        for (int o = 16; o; o >>= 1) c += __shfl_down_sync(0xFFFFFFFFu, c, o);
        if (lane == 0) red[warp] = c;
        __syncthreads();
        if (warp == 0) {
            int t = red[lane];
            #pragma unroll
            for (int o = 16; o; o >>= 1) t += __shfl_down_sync(0xFFFFFFFFu, t, o);
            if (lane == 0) red[32] = t;
        }
        __syncthreads();
        int tot = red[32];
        if (tot == k) { lo = mid; break; }     // exact interval found
        if (tot < k) hi = mid; else lo = mid + 1;
    }
    unsigned thr = lo;
    float t = __uint_as_float(thr);

    double s = 0.0;
    int c = 0;
    #pragma unroll
    for (int j = 0; j < 9; j++) {
        int i = tid + j * 1024;
        if (i < NP) {
            unsigned x = v[i];
            if (x > thr) { s += (double)__uint_as_float(x); c++; }
        }
    }
    #pragma unroll
    for (int o = 16; o; o >>= 1) {
        s += __shfl_down_sync(0xFFFFFFFFu, s, o);
        c += __shfl_down_sync(0xFFFFFFFFu, c, o);
    }
    if (lane == 0) { sred[warp] = s; red[warp] = c; }
    __syncthreads();
    if (warp == 0) {
        double S = sred[lane];
        int cc = red[lane];
        #pragma unroll
        for (int o = 16; o; o >>= 1) {
            S  += __shfl_down_sync(0xFFFFFFFFu, S, o);
            cc += __shfl_down_sync(0xFFFFFFFFu, cc, o);
        }
        if (lane == 0)
            atomicAdd(&g_hard_sum, S + (double)(k - cc) * (double)t);  // tie-exact
    }
}

// ---------------- final combine ----------------
__global__ void final_kernel(float* out) {
    double npos = (double)g_npos_total;
    double conf_loss = (g_hard_sum + g_pos_sum) / npos;
    long long d = 4LL * (long long)g_npos_total;
    if (d < 1) d = 1;
    double loc_loss = g_loc_sum / (double)d;
    out[0] = (float)(conf_loss + loc_loss);
}

// ---------------- launch ----------------
extern "C" void kernel_launch(void* const* d_in, const int* in_sizes, int n_in,
                              void* d_out, int out_size) {
    const float* plocs  = (const float*)d_in[0];  // [B,P,4]
    const float* scores = (const float*)d_in[1];  // [B,P,C]
    const float* boxes  = (const float*)d_in[2];  // [B,M,4]
    const int*   labels = (const int*)d_in[3];    // [B,M]
    const float* priors = (const float*)d_in[4];  // [P,4]

    init_kernel<<<(NB * NM + 255) / 256, 256>>>();

    dim3 gm((NP + 255) / 256, NB);
    match_kernel<<<gm, 256>>>((const float4*)boxes, (const float4*)priors);
    force_kernel<<<1, NB>>>();

    dim3 gl(NLB, NB);
    loss_kernel<<<gl, LBLK>>>((const float4*)plocs, scores,
                              (const float4*)boxes, labels,
                              (const float4*)priors);
    hardneg_kernel<<<NB, 1024>>>();
    final_kernel<<<1, 1>>>((float*)d_out);
}

// round 3
// speedup vs baseline: 1.9710x; 1.1471x over previous
#include <cuda_runtime.h>
#include <math.h>

#define NB 128
#define NP 8732
#define NM 16
#define NC 21
#define LBLK 128
#define NLB ((NP + LBLK - 1) / LBLK)   // 69

// ---------------- scratch ----------------
__device__ unsigned g_pack[NB * NP];       // (iou bits & ~0xF) | object
__device__ float    g_confneg[NB * NP];
__device__ unsigned long long g_best[NB * NM];
__device__ int    g_npos[NB];
__device__ int    g_npos_total;
__device__ double g_loc_sum;
__device__ double g_pos_sum;
__device__ double g_hard_sum;
__device__ int    g_done;

// ---------------- shared numeric helpers (bitwise-identical in fused & fixup) ----------------
__device__ __forceinline__ float ce_lse(const float* sv) {
    float mx = sv[0];
    #pragma unroll
    for (int c = 1; c < NC; c++) mx = fmaxf(mx, sv[c]);
    float se = 0.0f;
    #pragma unroll
    for (int c = 0; c < NC; c++) se += __expf(sv[c] - mx);
    return __logf(se) + mx;
}

__device__ __forceinline__ float loc_l1(float4 bx, float4 pr, float4 pl) {
    float cx = 0.5f * (bx.x + bx.z);
    float cy = 0.5f * (bx.y + bx.w);
    float cw = bx.z - bx.x;
    float ch = bx.w - bx.y;
    float g0 = (cx - pr.x) * 10.0f / pr.z;
    float g1 = (cy - pr.y) * 10.0f / pr.w;
    float g2 = __logf(cw / pr.z) * 5.0f;
    float g3 = __logf(ch / pr.w) * 5.0f;
    return fabsf(pl.x - g0) + fabsf(pl.y - g1) + fabsf(pl.z - g2) + fabsf(pl.w - g3);
}

// ---------------- init ----------------
__global__ void init_kernel() {
    int t = threadIdx.x;
    for (int i = t; i < NB * NM; i += 256) g_best[i] = 0ull;
    if (t < NB) g_npos[t] = 0;
    if (t == 0) {
        g_npos_total = 0;
        g_loc_sum = 0.0;
        g_pos_sum = 0.0;
        g_hard_sum = 0.0;
        g_done = 0;
    }
}

// ---------------- fused match + loss ----------------
// grid (69, 128), block 128.
__global__ void __launch_bounds__(128) fused_kernel(
        const float4* __restrict__ plocs,
        const float*  __restrict__ scores,
        const float4* __restrict__ boxes,
        const int*    __restrict__ labels,
        const float4* __restrict__ priors) {
    __shared__ float4 sbox[NM];
    __shared__ float  sarea[NM];
    __shared__ int    slab[NM];
    __shared__ unsigned skey[NM][LBLK];     // 8 KB
    __shared__ float  ssc[LBLK * NC];       // 10.75 KB
    __shared__ float  rl[4], rp[4];
    __shared__ int    rc[4];

    int b = blockIdx.y;
    int base = blockIdx.x * LBLK;
    int tid = threadIdx.x;
    int nval = NP - base; if (nval > LBLK) nval = LBLK;

    // fire-and-forget score staging (16B cp.async); (nval*21) % 4 == 0 always
    {
        const float4* src = (const float4*)(scores + ((size_t)b * NP + base) * NC);
        int nvec = (nval * NC) >> 2;
        for (int i = tid; i < nvec; i += LBLK) {
            unsigned sa = (unsigned)__cvta_generic_to_shared(&((float4*)ssc)[i]);
            asm volatile("cp.async.cg.shared.global [%0], [%1], 16;" :: "r"(sa), "l"(src + i));
        }
        asm volatile("cp.async.commit_group;");
    }

    if (tid < NM) {
        float4 bx = __ldg(&boxes[b * NM + tid]);
        sbox[tid] = bx;
        sarea[tid] = (bx.z - bx.x) * (bx.w - bx.y);
        slab[tid] = labels[b * NM + tid];
    }
    __syncthreads();

    int p = base + tid;
    bool valid = (tid < nval);

    float bestv = -1.0f;
    int   bestm = 0;
    float4 pr = make_float4(0.f, 0.f, 1.f, 1.f);
    if (valid) pr = __ldg(&priors[p]);
    {
        float px1 = pr.x - 0.5f * pr.z;
        float py1 = pr.y - 0.5f * pr.w;
        float px2 = pr.x + 0.5f * pr.z;
        float py2 = pr.y + 0.5f * pr.w;
        float pa  = pr.z * pr.w;
        #pragma unroll
        for (int m = 0; m < NM; m++) {
            float iou = 0.0f;
            if (valid) {
                float4 bx = sbox[m];
                float lx = fmaxf(bx.x, px1), ly = fmaxf(bx.y, py1);
                float rx = fminf(bx.z, px2), ry = fminf(bx.w, py2);
                float w = fmaxf(rx - lx, 0.0f), h = fmaxf(ry - ly, 0.0f);
                float inter = w * h;
                iou = __fdividef(inter, sarea[m] + pa - inter);
            }
            skey[m][tid] = __float_as_uint(iou);
            if (iou > bestv) { bestv = iou; bestm = m; }   // strict >: lowest m on ties
        }
    }
    if (valid)
        g_pack[b * NP + p] = (__float_as_uint(bestv) & 0xFFFFFFF0u) | (unsigned)bestm;
    __syncthreads();

    // per-object argmax over this tile -> global atomicMax (ties: lowest p)
    {
        int warp = tid >> 5, lane = tid & 31;
        #pragma unroll
        for (int mm = 0; mm < 4; mm++) {
            int m = warp * 4 + mm;
            unsigned long long best = 0ull;
            #pragma unroll
            for (int i = 0; i < 4; i++) {
                int idx = lane + i * 32;
                if (idx < nval) {
                    unsigned long long key = (((unsigned long long)skey[m][idx]) << 32)
                        | (unsigned long long)(0xFFFFFFFFu - (unsigned)(base + idx));
                    if (key > best) best = key;
                }
            }
            #pragma unroll
            for (int o = 16; o; o >>= 1) {
                unsigned long long other = __shfl_down_sync(0xFFFFFFFFu, best, o);
                if (other > best) best = other;
            }
            if (lane == 0) atomicMax(&g_best[b * NM + m], best);
        }
    }

    asm volatile("cp.async.wait_group 0;");
    __syncthreads();

    float locsum = 0.0f, possum = 0.0f;
    int cnt = 0;
    if (valid) {
        int idx = b * NP + p;
        int label = (bestv < 0.5f) ? 0 : slab[bestm];
        const float* sv = ssc + tid * NC;       // stride 21: conflict-free
        float lse = ce_lse(sv);
        float conf = lse - sv[label];
        if (label != 0) {
            cnt = 1;
            possum = conf;
            locsum = loc_l1(sbox[bestm], pr, __ldg(&plocs[idx]));
            g_confneg[idx] = 0.0f;
        } else {
            g_confneg[idx] = conf;
        }
    }

    int lane = tid & 31, warp = tid >> 5;
    #pragma unroll
    for (int o = 16; o; o >>= 1) {
        locsum += __shfl_down_sync(0xFFFFFFFFu, locsum, o);
        possum += __shfl_down_sync(0xFFFFFFFFu, possum, o);
        cnt    += __shfl_down_sync(0xFFFFFFFFu, cnt, o);
    }
    if (lane == 0) { rl[warp] = locsum; rp[warp] = possum; rc[warp] = cnt; }
    __syncthreads();
    if (tid == 0) {
        float L = rl[0] + rl[1] + rl[2] + rl[3];
        float Q = rp[0] + rp[1] + rp[2] + rp[3];
        int cc = rc[0] + rc[1] + rc[2] + rc[3];
        if (L != 0.0f) atomicAdd(&g_loc_sum, (double)L);
        if (Q != 0.0f) atomicAdd(&g_pos_sum, (double)Q);
        if (cc) {
            atomicAdd(&g_npos[b], cc);
            atomicAdd(&g_npos_total, cc);
        }
    }
}

// ---------------- fixup: apply force-assign deltas for <=16 priors per row ----------------
// grid 128, block 32 (one warp per batch row)
__global__ void fixup_kernel(
        const float4* __restrict__ plocs,
        const float*  __restrict__ scores,
        const float4* __restrict__ boxes,
        const int*    __restrict__ labels,
        const float4* __restrict__ priors) {
    int b = blockIdx.x;
    int lane = threadIdx.x;

    int p = -1;
    if (lane < NM) {
        unsigned long long k = g_best[b * NM + lane];
        p = (int)(0xFFFFFFFFu - (unsigned)(k & 0xFFFFFFFFull));
    }
    // dedupe: sequential-scatter semantics -> highest m wins for duplicate p
    bool active = (lane < NM);
    #pragma unroll
    for (int o = 0; o < NM; o++) {
        int po = __shfl_sync(0xFFFFFFFFu, p, o);
        if (o > lane && po == p) active = false;
    }

    float d_loc = 0.0f, d_pos = 0.0f;
    int d_np = 0;
    if (active) {
        int idx = b * NP + p;
        unsigned pk = g_pack[idx];
        float ov_old = __uint_as_float(pk & 0xFFFFFFF0u);
        int obj_old = (int)(pk & 0xFu);
        int label_old = (ov_old < 0.5f) ? 0 : labels[b * NM + obj_old];
        int label_new = labels[b * NM + lane];      // >= 1

        float sv[NC];
        const float* s = scores + (size_t)idx * NC;
        #pragma unroll
        for (int c = 0; c < NC; c++) sv[c] = s[c];
        float lse = ce_lse(sv);

        float4 pr = __ldg(&priors[p]);
        float4 pl = __ldg(&plocs[idx]);
        float loc_new = loc_l1(__ldg(&boxes[b * NM + lane]), pr, pl);

        if (label_old != 0) {
            // was already positive: conf changes only via label; loc via object
            d_pos = (lse - sv[label_new]) - (lse - sv[label_old]);
            d_loc = loc_new - loc_l1(__ldg(&boxes[b * NM + obj_old]), pr, pl);
        } else {
            d_pos = lse - sv[label_new];
            d_loc = loc_new;
            d_np = 1;
            g_confneg[idx] = 0.0f;   // remove from negative pool
        }
    }

    #pragma unroll
    for (int o = 16; o; o >>= 1) {
        d_loc += __shfl_down_sync(0xFFFFFFFFu, d_loc, o);
        d_pos += __shfl_down_sync(0xFFFFFFFFu, d_pos, o);
        d_np  += __shfl_down_sync(0xFFFFFFFFu, d_np, o);
    }
    if (lane == 0) {
        if (d_loc != 0.0f) atomicAdd(&g_loc_sum, (double)d_loc);
        if (d_pos != 0.0f) atomicAdd(&g_pos_sum, (double)d_pos);
        if (d_np) {
            atomicAdd(&g_npos[b], d_np);
            atomicAdd(&g_npos_total, d_np);
        }
    }
}

// ---------------- hard-negative mining: 3-level radix histogram + fused final ----------------
__device__ __forceinline__ void find_bucket(const int* hist, int nbuckets, int k,
                                            int lane, int* fb) {
    int chunk = nbuckets >> 5;
    int base = lane * chunk;
    int cs = 0;
    for (int i = 0; i < chunk; i++) cs += hist[base + i];
    int incl = cs;
    #pragma unroll
    for (int o = 1; o < 32; o <<= 1) {
        int t = __shfl_down_sync(0xFFFFFFFFu, incl, o);
        if (lane + o < 32) incl += t;
    }
    int excl = incl - cs;
    bool hit = (excl < k) && (k <= incl);
    unsigned ball = __ballot_sync(0xFFFFFFFFu, hit);
    int j = __ffs(ball) - 1;
    if (lane == j) {
        int acc = excl;
        for (int i = chunk - 1; i >= 0; i--) {
            int h = hist[base + i];
            if (acc + h >= k) { fb[0] = base + i; fb[1] = k - acc; break; }
            acc += h;
        }
    }
}

__global__ void __launch_bounds__(1024, 1) hardneg_final_kernel(float* out) {
    __shared__ unsigned v[NP];        // 34928 B
    __shared__ int hist[2048];        // 8192 B
    __shared__ int fb[2];
    __shared__ double sred[32];
    __shared__ int red[32];

    int b = blockIdx.x;
    int tid = threadIdx.x;
    int lane = tid & 31, warp = tid >> 5;

    for (int i = tid; i < NP; i += 1024) v[i] = __float_as_uint(g_confneg[b * NP + i]);
    for (int i = tid; i < 2048; i += 1024) hist[i] = 0;
    __syncthreads();

    int k = 3 * g_npos[b];
    if (k > NP) k = NP;

    // level 1: top 11 bits (sign always 0)
    for (int i = tid; i < NP; i += 1024) atomicAdd(&hist[v[i] >> 20], 1);
    __syncthreads();
    if (warp == 0) find_bucket(hist, 2048, k, lane, fb);
    __syncthreads();
    unsigned B1 = (unsigned)fb[0];
    int r = fb[1];
    for (int i = tid; i < 2048; i += 1024) hist[i] = 0;
    __syncthreads();

    // level 2: next 11 bits among bucket B1
    for (int i = tid; i < NP; i += 1024) {
        unsigned x = v[i];
        if ((x >> 20) == B1) atomicAdd(&hist[(x >> 9) & 0x7FFu], 1);
    }
    __syncthreads();
    if (warp == 0) find_bucket(hist, 2048, r, lane, fb);
    __syncthreads();
    unsigned pfx = (B1 << 11) | (unsigned)fb[0];
    r = fb[1];
    for (int i = tid; i < 512; i += 1024) hist[i] = 0;
    __syncthreads();

    // level 3: low 9 bits among prefix pfx
    for (int i = tid; i < NP; i += 1024) {
        unsigned x = v[i];
        if ((x >> 9) == pfx) atomicAdd(&hist[x & 0x1FFu], 1);
    }
    __syncthreads();
    if (warp == 0) find_bucket(hist, 512, r, lane, fb);
    __syncthreads();
    unsigned thr = (pfx << 9) | (unsigned)fb[0];   // exact kth-largest bit pattern

    // exact top-k sum: strictly greater + tie copies of thr
    double s = 0.0;
    int c = 0;
    #pragma unroll
    for (int j = 0; j < 9; j++) {
        int i = tid + j * 1024;
        if (i < NP) {
            unsigned x = v[i];
            if (x > thr) { s += (double)__uint_as_float(x); c++; }
        }
    }
    #pragma unroll
    for (int o = 16; o; o >>= 1) {
        s += __shfl_down_sync(0xFFFFFFFFu, s, o);
        c += __shfl_down_sync(0xFFFFFFFFu, c, o);
    }
    if (lane == 0) { sred[warp] = s; red[warp] = c; }
    __syncthreads();
    if (warp == 0) {
        double S = sred[lane];
        int C = red[lane];
        #pragma unroll
        for (int o = 16; o; o >>= 1) {
            S += __shfl_down_sync(0xFFFFFFFFu, S, o);
            C += __shfl_down_sync(0xFFFFFFFFu, C, o);
        }
        if (lane == 0)
            atomicAdd(&g_hard_sum, S + (double)(k - C) * (double)__uint_as_float(thr));
    }
    __syncthreads();

    // fused final combine: last block writes the scalar
    if (tid == 0) {
        __threadfence();
        if (atomicAdd(&g_done, 1) == NB - 1) {
            __threadfence();
            double npos = (double)g_npos_total;
            double conf_loss = (g_hard_sum + g_pos_sum) / npos;
            long long d = 4LL * (long long)g_npos_total;
            if (d < 1) d = 1;
            out[0] = (float)(conf_loss + g_loc_sum / (double)d);
        }
    }
}

// ---------------- launch ----------------
extern "C" void kernel_launch(void* const* d_in, const int* in_sizes, int n_in,
                              void* d_out, int out_size) {
    const float* plocs  = (const float*)d_in[0];  // [B,P,4]
    const float* scores = (const float*)d_in[1];  // [B,P,C]
    const float* boxes  = (const float*)d_in[2];  // [B,M,4]
    const int*   labels = (const int*)d_in[3];    // [B,M]
    const float* priors = (const float*)d_in[4];  // [P,4]

    init_kernel<<<1, 256>>>();
    dim3 g(NLB, NB);
    fused_kernel<<<g, LBLK>>>((const float4*)plocs, scores,
                              (const float4*)boxes, labels,
                              (const float4*)priors);
    fixup_kernel<<<NB, 32>>>((const float4*)plocs, scores,
                             (const float4*)boxes, labels,
                             (const float4*)priors);
    hardneg_final_kernel<<<NB, 1024>>>((float*)d_out);
}